// round 1
// baseline (speedup 1.0000x reference)
#include <cuda_runtime.h>

#define N_NODES 100000
#define N_EDGES 3200000
#define FEAT_IN 512
#define FEAT_H  128
#define FEAT_O  40
#define NV4     10          // FEAT_O / 4
#define K_ITERS 20
#define ALPHA_F 0.1f

// ---------------- static scratch (no allocation allowed) ----------------
__device__ float  g_h1[(size_t)N_NODES * FEAT_H];   // 51.2 MB
__device__ float4 g_h0[N_NODES * NV4];              // 16 MB
__device__ float4 g_zA[N_NODES * NV4];              // 16 MB
__device__ float4 g_zB[N_NODES * NV4];              // 16 MB
__device__ int    g_deg[N_NODES];
__device__ float  g_dinv[N_NODES];
__device__ int    g_rowptr[N_NODES + 1];
__device__ int    g_cursor[N_NODES];
__device__ int    g_src[N_EDGES];                   // 12.8 MB
__device__ float  g_w[N_EDGES];                     // 12.8 MB

// ---------------- degree histogram ----------------
__global__ void k_deg(const int* __restrict__ col, int E) {
    int i = blockIdx.x * blockDim.x + threadIdx.x;
    if (i < E) atomicAdd(&g_deg[col[i]], 1);
}

__global__ void k_dinv(int N) {
    int i = blockIdx.x * blockDim.x + threadIdx.x;
    if (i < N) g_dinv[i] = rsqrtf((float)(g_deg[i] + 1));  // +1 = self loop
}

// ---------------- single-block exclusive scan over degrees ----------------
__global__ void k_scan(int N) {
    __shared__ int sm[1024];
    int t = threadIdx.x;
    int chunk = (N + 1023) >> 10;
    int start = t * chunk;
    int stop  = min(start + chunk, N);
    int s = 0;
    for (int i = start; i < stop; i++) s += g_deg[i];
    sm[t] = s;
    __syncthreads();
    for (int off = 1; off < 1024; off <<= 1) {
        int v = (t >= off) ? sm[t - off] : 0;
        __syncthreads();
        sm[t] += v;
        __syncthreads();
    }
    int run = (t == 0) ? 0 : sm[t - 1];
    for (int i = start; i < stop; i++) {
        g_rowptr[i] = run;
        g_cursor[i] = run;
        run += g_deg[i];
    }
    if (t == 1023) g_rowptr[N] = sm[1023];
}

// ---------------- scatter edges into dest-sorted CSR ----------------
__global__ void k_scatter(const int* __restrict__ row, const int* __restrict__ col, int E) {
    int e = blockIdx.x * blockDim.x + threadIdx.x;
    if (e < E) {
        int c = col[e];
        int r = row[e];
        int p = atomicAdd(&g_cursor[c], 1);
        g_src[p] = r;
        g_w[p]   = g_dinv[r];
    }
}

// ---------------- GEMM1: h1 = relu(x[ N,512 ] @ W1[512,128] + b1) ----------------
// BM=64, BN=128, BK=16, 256 threads, 8x4 micro-tile
__global__ void k_gemm1(const float* __restrict__ x, const float* __restrict__ W1,
                        const float* __restrict__ b1, int N) {
    __shared__ float As[16][68];
    __shared__ float Bs[16][128];
    int tid  = threadIdx.x;
    int row0 = blockIdx.x * 64;
    int ty = tid >> 5;        // 0..7  -> rows ty*8 .. ty*8+7
    int tx = tid & 31;        // 0..31 -> cols tx*4 .. tx*4+3
    float acc[8][4];
    #pragma unroll
    for (int i = 0; i < 8; i++)
        #pragma unroll
        for (int j = 0; j < 4; j++) acc[i][j] = 0.f;

    int a_r = tid >> 2;             // 0..63
    int a_c = (tid & 3) << 2;       // 0,4,8,12
    int b_r = tid >> 4;             // 0..15
    int b_c = (tid & 15) << 3;      // 0..120

    for (int k0 = 0; k0 < FEAT_IN; k0 += 16) {
        float4 av = make_float4(0.f, 0.f, 0.f, 0.f);
        int gr = row0 + a_r;
        if (gr < N)
            av = *reinterpret_cast<const float4*>(&x[(size_t)gr * FEAT_IN + k0 + a_c]);
        As[a_c + 0][a_r] = av.x;
        As[a_c + 1][a_r] = av.y;
        As[a_c + 2][a_r] = av.z;
        As[a_c + 3][a_r] = av.w;

        const float* wp = &W1[(size_t)(k0 + b_r) * FEAT_H + b_c];
        float4 bv0 = *reinterpret_cast<const float4*>(wp);
        float4 bv1 = *reinterpret_cast<const float4*>(wp + 4);
        *reinterpret_cast<float4*>(&Bs[b_r][b_c])     = bv0;
        *reinterpret_cast<float4*>(&Bs[b_r][b_c + 4]) = bv1;
        __syncthreads();

        #pragma unroll
        for (int kk = 0; kk < 16; kk++) {
            float4 bb = *reinterpret_cast<const float4*>(&Bs[kk][tx * 4]);
            #pragma unroll
            for (int i = 0; i < 8; i++) {
                float a = As[kk][ty * 8 + i];
                acc[i][0] = fmaf(a, bb.x, acc[i][0]);
                acc[i][1] = fmaf(a, bb.y, acc[i][1]);
                acc[i][2] = fmaf(a, bb.z, acc[i][2]);
                acc[i][3] = fmaf(a, bb.w, acc[i][3]);
            }
        }
        __syncthreads();
    }
    float4 bias = *reinterpret_cast<const float4*>(&b1[tx * 4]);
    #pragma unroll
    for (int i = 0; i < 8; i++) {
        int gr = row0 + ty * 8 + i;
        if (gr < N) {
            float4 o;
            o.x = fmaxf(acc[i][0] + bias.x, 0.f);
            o.y = fmaxf(acc[i][1] + bias.y, 0.f);
            o.z = fmaxf(acc[i][2] + bias.z, 0.f);
            o.w = fmaxf(acc[i][3] + bias.w, 0.f);
            *reinterpret_cast<float4*>(&g_h1[(size_t)gr * FEAT_H + tx * 4]) = o;
        }
    }
}

// ---------------- GEMM2: h0 = relu(h1[ N,128 ] @ W2[128,40] + b2) ----------------
// 320 threads = 8 rows x 40 cols; block handles 64 rows (8 groups)
__global__ void k_gemm2(const float* __restrict__ W2, const float* __restrict__ b2, int N) {
    __shared__ float Ws[FEAT_H * FEAT_O];
    __shared__ float b2s[FEAT_O];
    __shared__ float hs[8 * FEAT_H];
    int tid = threadIdx.x;
    for (int i = tid; i < FEAT_H * FEAT_O; i += 320) Ws[i] = W2[i];
    if (tid < FEAT_O) b2s[tid] = b2[tid];
    int r = tid / FEAT_O;   // 0..7
    int c = tid % FEAT_O;   // 0..39
    float* h0f = reinterpret_cast<float*>(g_h0);
    for (int rg = 0; rg < 8; rg++) {
        int rowbase = blockIdx.x * 64 + rg * 8;
        __syncthreads();
        for (int i = tid; i < 8 * FEAT_H; i += 320) {
            int rr = i >> 7, cc = i & 127;
            int grow = rowbase + rr;
            hs[i] = (grow < N) ? g_h1[(size_t)grow * FEAT_H + cc] : 0.f;
        }
        __syncthreads();
        float acc = b2s[c];
        #pragma unroll 8
        for (int k = 0; k < FEAT_H; k++)
            acc = fmaf(hs[r * FEAT_H + k], Ws[k * FEAT_O + c], acc);
        int grow = rowbase + r;
        if (grow < N) h0f[(size_t)grow * FEAT_O + c] = fmaxf(acc, 0.f);
    }
}

// ---------------- propagation step: one warp per destination node ----------------
// z_new[i] = 0.9*dinv[i]*( sum_e dinv[src]*z[src] + dinv[i]*z[i] ) + 0.1*h0[i]
__global__ void k_prop(const float4* __restrict__ zin, float4* __restrict__ zout, int N) {
    int warp = (blockIdx.x * blockDim.x + threadIdx.x) >> 5;
    if (warp >= N) return;
    int lane = threadIdx.x & 31;
    int g = lane / 10;            // group 0..2 (3 for lanes 30,31)
    int q = lane - g * 10;        // float4 index within row
    bool active = lane < 30;

    int beg = g_rowptr[warp];
    int end = g_rowptr[warp + 1];

    float4 acc = make_float4(0.f, 0.f, 0.f, 0.f);
    for (int j = beg; j < end; j += 3) {
        int e = j + g;
        if (active && e < end) {
            int   s = __ldg(&g_src[e]);
            float w = __ldg(&g_w[e]);
            float4 v = zin[s * NV4 + q];
            acc.x = fmaf(w, v.x, acc.x);
            acc.y = fmaf(w, v.y, acc.y);
            acc.z = fmaf(w, v.z, acc.z);
            acc.w = fmaf(w, v.w, acc.w);
        }
    }
    const unsigned FULL = 0xffffffffu;
    float ax = acc.x + __shfl_sync(FULL, acc.x, lane + 10) + __shfl_sync(FULL, acc.x, lane + 20);
    float ay = acc.y + __shfl_sync(FULL, acc.y, lane + 10) + __shfl_sync(FULL, acc.y, lane + 20);
    float az = acc.z + __shfl_sync(FULL, acc.z, lane + 10) + __shfl_sync(FULL, acc.z, lane + 20);
    float aw = acc.w + __shfl_sync(FULL, acc.w, lane + 10) + __shfl_sync(FULL, acc.w, lane + 20);

    if (lane < 10) {
        float di = g_dinv[warp];
        float4 zi = zin[warp * NV4 + q];
        float4 h  = g_h0[warp * NV4 + q];
        float s9 = (1.f - ALPHA_F) * di;
        float4 o;
        o.x = fmaf(s9, ax + di * zi.x, ALPHA_F * h.x);
        o.y = fmaf(s9, ay + di * zi.y, ALPHA_F * h.y);
        o.z = fmaf(s9, az + di * zi.z, ALPHA_F * h.z);
        o.w = fmaf(s9, aw + di * zi.w, ALPHA_F * h.w);
        zout[warp * NV4 + q] = o;
    }
}

// ---------------- launch ----------------
extern "C" void kernel_launch(void* const* d_in, const int* in_sizes, int n_in,
                              void* d_out, int out_size) {
    const float* x  = (const float*)d_in[0];
    const int*   ei = (const int*)d_in[1];
    const float* W1 = (const float*)d_in[2];
    const float* b1 = (const float*)d_in[3];
    const float* W2 = (const float*)d_in[4];
    const float* b2 = (const float*)d_in[5];
    int N = N_NODES;
    int E = in_sizes[1] / 2;
    const int* row = ei;        // sources
    const int* col = ei + E;    // targets

    void* p;
    cudaGetSymbolAddress(&p, g_deg);
    cudaMemsetAsync(p, 0, N * sizeof(int));

    k_deg    <<<(E + 255) / 256, 256>>>(col, E);
    k_dinv   <<<(N + 255) / 256, 256>>>(N);
    k_scan   <<<1, 1024>>>(N);
    k_scatter<<<(E + 255) / 256, 256>>>(row, col, E);

    k_gemm1<<<(N + 63) / 64, 256>>>(x, W1, b1, N);
    k_gemm2<<<(N + 63) / 64, 320>>>(W2, b2, N);

    float4 *bufA, *bufB, *h0p;
    cudaGetSymbolAddress(&p, g_zA); bufA = (float4*)p;
    cudaGetSymbolAddress(&p, g_zB); bufB = (float4*)p;
    cudaGetSymbolAddress(&p, g_h0); h0p  = (float4*)p;
    float4* bufs[2] = {bufA, bufB};

    int blocks = (N * 32 + 255) / 256;   // one warp per node
    for (int k = 0; k < K_ITERS; k++) {
        const float4* zin = (k == 0) ? h0p : bufs[k & 1];
        float4* zout = (k == K_ITERS - 1) ? (float4*)d_out : bufs[(k + 1) & 1];
        k_prop<<<blocks, 256>>>(zin, zout, N);
    }
}